// round 10
// baseline (speedup 1.0000x reference)
#include <cuda_runtime.h>
#include <math.h>
#include <stdint.h>

// Fixed problem shape
#define BB 16
#define HH 544
#define WW 960
#define NTOT (BB * HH * WW)              // 8,355,840
#define N4   (NTOT / 4)                  // 2,088,960 float4 chunks
#define THREADS 256
#define NCHUNK (N4 / THREADS)            // 8160 chunks of 256 float4s
#define GRID (148 * 8)                   // 1184 blocks, 8/SM, one exact wave
#define ITEMS_LO 6
#define REM (NCHUNK - ITEMS_LO * GRID)   // 1056 blocks do 7 items, 128 do 6
#define STAGES 2

// Global accumulators: [0]=count, [1]=sum sl1(dl-dlgt)*m, [2]=sum sl1(recon-lgt)*m
__device__ double   g_acc[3];
__device__ unsigned g_done;

__device__ __forceinline__ float smooth_l1(float d) {
    float ad = fabsf(d);
    return (ad < 1.0f) ? 0.5f * ad * ad : ad - 0.5f;
}

__device__ __forceinline__ void cpa16(uint32_t saddr, const void* gaddr) {
    asm volatile("cp.async.cg.shared.global [%0], [%1], 16;" :: "r"(saddr), "l"(gaddr));
}
#define CP_COMMIT() asm volatile("cp.async.commit_group;")
#define CP_WAIT(n)  asm volatile("cp.async.wait_group %0;" :: "n"(n))

__global__ void __launch_bounds__(THREADS, 8)
fused_loss_kernel(const float* __restrict__ dl,
                  const float* __restrict__ seg,
                  const float* __restrict__ dlgt,
                  const float* __restrict__ lgt,
                  float* __restrict__ out)
{
    // double-buffered staging: [stage][array(dl,lgt,dlgt)][thread]
    __shared__ __align__(16) float4 sbuf[STAGES][3][THREADS];

    const int tid = threadIdx.x;
    const int bid = blockIdx.x;
    const int nitems = (bid < REM) ? (ITEMS_LO + 1) : ITEMS_LO;

    const uint32_t sb0  = (uint32_t)__cvta_generic_to_shared(&sbuf[0][0][tid]);
    const uint32_t A_STR = THREADS * 16u;        // bytes between arrays in a stage
    const uint32_t S_STR = 3u * A_STR;           // bytes between stages

    const float4* __restrict__ dl4 = reinterpret_cast<const float4*>(dl);
    const float4* __restrict__ lg4 = reinterpret_cast<const float4*>(lgt);
    const float4* __restrict__ gt4 = reinterpret_cast<const float4*>(dlgt);

    // ---- prologue: issue stage 0 (item 0) ----
    {
        const int i4a = bid * THREADS + tid;
        cpa16(sb0 + 0 * A_STR, dl4 + i4a);
        cpa16(sb0 + 1 * A_STR, lg4 + i4a);
        cpa16(sb0 + 2 * A_STR, gt4 + i4a);
        CP_COMMIT();
    }

    int   icnt = 0;
    float sd = 0.0f, sr = 0.0f;
    int   i4 = bid * THREADS + tid;

    for (int j = 0; j < nitems; j++) {
        // issue item j+1 into the other buffer, then wait for item j
        if (j + 1 < nitems) {
            const uint32_t sb = sb0 + (uint32_t)((j + 1) & 1) * S_STR;
            const int ipre = i4 + GRID * THREADS;
            cpa16(sb + 0 * A_STR, dl4 + ipre);
            cpa16(sb + 1 * A_STR, lg4 + ipre);
            cpa16(sb + 2 * A_STR, gt4 + ipre);
            CP_COMMIT();
            CP_WAIT(1);               // item j landed; item j+1 in flight
        } else {
            CP_WAIT(0);
        }

        // consume current stage (thread-private slots; no barrier)
        const int stC = j & 1;
        const float4 dv = sbuf[stC][0][tid];
        const float4 lv = sbuf[stC][1][tid];
        const float4 gv = sbuf[stC][2][tid];

        const int idx = i4 * 4;
        const int row = idx / WW;                 // const-div -> mul-hi
        const int wb  = idx - row * WW;
        const float* __restrict__ s = seg + row * WW;
        const float wf = (float)wb;

        #pragma unroll
        for (int k = 0; k < 4; k++) {
            const float d  = (&dv.x)[k];
            const float l  = (&lv.x)[k];
            const float dg = (&gv.x)[k];
            const bool  msk = (l > 0.0f);

            const float t0 = smooth_l1(d - dg);

            // horizontal bilinear warp at (w - d), zeros padding
            const float sx  = (wf + (float)k) - d;
            const float x0f = floorf(sx);
            const float wx  = sx - x0f;
            const int   x0i = (int)x0f;
            const int   x1i = x0i + 1;
            // d >= 0 -> x0i <= w < W: only lower bound needed for g0
            const float g0 = (msk & (x0i >= 0))                     ? __ldg(s + x0i) : 0.0f;
            const float g1 = (msk & ((unsigned)x1i < (unsigned)WW)) ? __ldg(s + x1i) : 0.0f;
            const float warped = (1.0f - wx) * g0 + wx * g1;

            const float recon = __fdividef(1.0f, 1.0f + __expf(-warped));
            const float t1 = smooth_l1(recon - l);

            if (msk) {
                icnt += 1;
                sd   += t0;
                sr   += t1;
            }
        }

        i4 += GRID * THREADS;
    }

    float cnt = (float)icnt;

    // ---- Block reduction: warp shuffles -> shared -> fp64 atomics ----
    #pragma unroll
    for (int off = 16; off > 0; off >>= 1) {
        cnt += __shfl_down_sync(0xffffffffu, cnt, off);
        sd  += __shfl_down_sync(0xffffffffu, sd,  off);
        sr  += __shfl_down_sync(0xffffffffu, sr,  off);
    }

    __shared__ float s_cnt[THREADS / 32];
    __shared__ float s_sd [THREADS / 32];
    __shared__ float s_sr [THREADS / 32];

    const int lane = tid & 31;
    const int wid  = tid >> 5;
    if (lane == 0) { s_cnt[wid] = cnt; s_sd[wid] = sd; s_sr[wid] = sr; }
    __syncthreads();

    if (wid == 0) {
        cnt = (lane < THREADS / 32) ? s_cnt[lane] : 0.0f;
        sd  = (lane < THREADS / 32) ? s_sd [lane] : 0.0f;
        sr  = (lane < THREADS / 32) ? s_sr [lane] : 0.0f;
        #pragma unroll
        for (int off = 4; off > 0; off >>= 1) {
            cnt += __shfl_down_sync(0xffffffffu, cnt, off);
            sd  += __shfl_down_sync(0xffffffffu, sd,  off);
            sr  += __shfl_down_sync(0xffffffffu, sr,  off);
        }
        if (lane == 0) {
            atomicAdd(&g_acc[0], (double)cnt);
            atomicAdd(&g_acc[1], (double)sd);
            atomicAdd(&g_acc[2], (double)sr);

            // ---- Last-block finalize (fused) ----
            __threadfence();
            const unsigned ticket = atomicAdd(&g_done, 1u);
            if (ticket == GRID - 1) {
                const double tc = g_acc[0];
                const double ts = g_acc[1];
                const double tr = g_acc[2];

                float loss = (float)(ts / tc);
                if (isnan(loss)) loss = 0.0f;
                const float loss_recon = (float)(tr / tc);
                out[0] = loss + 0.5f * loss_recon;

                g_acc[0] = 0.0;
                g_acc[1] = 0.0;
                g_acc[2] = 0.0;
                g_done   = 0u;
            }
        }
    }
}

extern "C" void kernel_launch(void* const* d_in, const int* in_sizes, int n_in,
                              void* d_out, int out_size)
{
    const float* dl   = (const float*)d_in[0];
    const float* seg  = (const float*)d_in[1];
    const float* dlgt = (const float*)d_in[2];
    const float* lgt  = (const float*)d_in[3];
    float* out = (float*)d_out;

    fused_loss_kernel<<<GRID, THREADS>>>(dl, seg, dlgt, lgt, out);
}

// round 11
// speedup vs baseline: 1.2991x; 1.2991x over previous
#include <cuda_runtime.h>
#include <math.h>

// Fixed problem shape
#define BB 16
#define HH 544
#define WW 960
#define NTOT (BB * HH * WW)              // 8,355,840
#define N4   (NTOT / 4)                  // 2,088,960 float4 chunks
#define THREADS 256
#define ITEMS 8
#define GRID (N4 / (THREADS * ITEMS))    // 1020 blocks (exact; <= 148*7 => single wave)
#define STRIDE (GRID * THREADS)          // 261,120 float4s between items

// Global accumulators: [0]=count, [1]=sum sl1(dl-dlgt)*m, [2]=sum sl1(recon-lgt)*m
__device__ double   g_acc[3];
__device__ unsigned g_done;

__device__ __forceinline__ float smooth_l1(float d) {
    float ad = fabsf(d);
    return (ad < 1.0f) ? 0.5f * ad * ad : ad - 0.5f;
}

__global__ void __launch_bounds__(THREADS, 7)
fused_loss_kernel(const float* __restrict__ dl,
                  const float* __restrict__ seg,
                  const float* __restrict__ dlgt,
                  const float* __restrict__ lgt,
                  float* __restrict__ out)
{
    const int tid = threadIdx.x;
    const float4* __restrict__ dl4 = reinterpret_cast<const float4*>(dl);
    const float4* __restrict__ lg4 = reinterpret_cast<const float4*>(lgt);
    const float4* __restrict__ gt4 = reinterpret_cast<const float4*>(dlgt);

    float cnt = 0.0f, sd = 0.0f, sr = 0.0f;

    int i4 = blockIdx.x * THREADS + tid;

    // ---- software pipeline: depth-1 prologue ----
    float4 dv = __ldcs(dl4 + i4);
    float4 lv = __ldcs(lg4 + i4);
    float4 gv = __ldcs(gt4 + i4);

    #pragma unroll
    for (int it = 0; it < ITEMS; it++) {
        // prefetch next item while computing this one
        float4 dvn, lvn, gvn;
        const int inext = i4 + STRIDE;
        if (it + 1 < ITEMS) {
            dvn = __ldcs(dl4 + inext);
            lvn = __ldcs(lg4 + inext);
            gvn = __ldcs(gt4 + inext);
        }

        const int idx = i4 * 4;
        const int row = idx / WW;                 // const-div -> mul-hi
        const int wb  = idx - row * WW;
        const float* __restrict__ s = seg + row * WW;
        const float wf = (float)wb;

        // ---- phase 1: issue ALL gathers up front (depend only on dv) ----
        // gathers are NOT gated by the lgt mask: latencies overlap each other
        // instead of serializing behind the MUFU chain; masked lanes are
        // discarded by the select in phase 2 (matches reference semantics).
        float g0a[4], g1a[4], wxa[4];
        #pragma unroll
        for (int k = 0; k < 4; k++) {
            const float d   = (&dv.x)[k];
            const float sx  = (wf + (float)k) - d;
            const float x0f = floorf(sx);
            wxa[k] = sx - x0f;
            const int x0i = (int)x0f;
            const int x1i = x0i + 1;
            // d >= 0 -> x0i <= w < W: only lower bound needed for g0
            g0a[k] = (x0i >= 0)                     ? __ldg(s + x0i) : 0.0f;
            g1a[k] = ((unsigned)x1i < (unsigned)WW) ? __ldg(s + x1i) : 0.0f;
        }

        // ---- phase 2: MUFU chain + masked accumulation ----
        #pragma unroll
        for (int k = 0; k < 4; k++) {
            const float d  = (&dv.x)[k];
            const float l  = (&lv.x)[k];
            const float dg = (&gv.x)[k];
            const bool  msk = (l > 0.0f);

            const float t0 = smooth_l1(d - dg);

            const float wx = wxa[k];
            const float warped = (1.0f - wx) * g0a[k] + wx * g1a[k];
            const float recon  = __fdividef(1.0f, 1.0f + __expf(-warped));
            const float t1 = smooth_l1(recon - l);

            cnt += msk ? 1.0f : 0.0f;
            sd  += msk ? t0   : 0.0f;
            sr  += msk ? t1   : 0.0f;
        }

        dv = dvn; lv = lvn; gv = gvn;
        i4 = inext;
    }

    // ---- Block reduction: warp shuffles -> shared -> fp64 atomics ----
    #pragma unroll
    for (int off = 16; off > 0; off >>= 1) {
        cnt += __shfl_down_sync(0xffffffffu, cnt, off);
        sd  += __shfl_down_sync(0xffffffffu, sd,  off);
        sr  += __shfl_down_sync(0xffffffffu, sr,  off);
    }

    __shared__ float s_cnt[THREADS / 32];
    __shared__ float s_sd [THREADS / 32];
    __shared__ float s_sr [THREADS / 32];

    const int lane = tid & 31;
    const int wid  = tid >> 5;
    if (lane == 0) { s_cnt[wid] = cnt; s_sd[wid] = sd; s_sr[wid] = sr; }
    __syncthreads();

    if (wid == 0) {
        cnt = (lane < THREADS / 32) ? s_cnt[lane] : 0.0f;
        sd  = (lane < THREADS / 32) ? s_sd [lane] : 0.0f;
        sr  = (lane < THREADS / 32) ? s_sr [lane] : 0.0f;
        #pragma unroll
        for (int off = 4; off > 0; off >>= 1) {
            cnt += __shfl_down_sync(0xffffffffu, cnt, off);
            sd  += __shfl_down_sync(0xffffffffu, sd,  off);
            sr  += __shfl_down_sync(0xffffffffu, sr,  off);
        }
        if (lane == 0) {
            atomicAdd(&g_acc[0], (double)cnt);
            atomicAdd(&g_acc[1], (double)sd);
            atomicAdd(&g_acc[2], (double)sr);

            // ---- Last-block finalize (fused) ----
            __threadfence();
            const unsigned ticket = atomicAdd(&g_done, 1u);
            if (ticket == GRID - 1) {
                const double tc = g_acc[0];
                const double ts = g_acc[1];
                const double tr = g_acc[2];

                float loss = (float)(ts / tc);
                if (isnan(loss)) loss = 0.0f;
                const float loss_recon = (float)(tr / tc);
                out[0] = loss + 0.5f * loss_recon;

                g_acc[0] = 0.0;
                g_acc[1] = 0.0;
                g_acc[2] = 0.0;
                g_done   = 0u;
            }
        }
    }
}

extern "C" void kernel_launch(void* const* d_in, const int* in_sizes, int n_in,
                              void* d_out, int out_size)
{
    const float* dl   = (const float*)d_in[0];
    const float* seg  = (const float*)d_in[1];
    const float* dlgt = (const float*)d_in[2];
    const float* lgt  = (const float*)d_in[3];
    float* out = (float*)d_out;

    fused_loss_kernel<<<GRID, THREADS>>>(dl, seg, dlgt, lgt, out);
}